// round 1
// baseline (speedup 1.0000x reference)
#include <cuda_runtime.h>

// Problem constants
#define AP 48        // paths
#define LL 64        // length
#define DD 64        // channels
#define MM 63        // L-1 (increments)
#define PER_GRAM (AP*AP)          // 2304
#define NPAIRS (3*PER_GRAM)       // 6912
#define INC_STRIDE (63*64)        // padded row stride 64, 63 rows

// Static scratch (no allocation allowed)
__device__ float g_inc[(size_t)NPAIRS * INC_STRIDE];   // ~111.5 MB
__device__ float g_K[NPAIRS];

// ---------------------------------------------------------------------------
// Kernel 1: per-pair increment Gram  inc[i][j] = dX[a,i] . dY[b,j]
// One CTA (128 threads) per pair. Skips a>b for the symmetric XX/YY grams.
// smem tiles stored transposed [d][i] with stride 65 -> conflict-free LDS.
// ---------------------------------------------------------------------------
__global__ void __launch_bounds__(128, 4) gemm_kernel(
    const float* __restrict__ X, const float* __restrict__ Y)
{
    const int p = blockIdx.x;
    const int gram = p / PER_GRAM;
    const int r = p % PER_GRAM;
    const int a = r / AP, b = r % AP;
    if (gram < 2 && a > b) return;   // symmetric grams: upper triangle only

    const float* __restrict__ P = (gram == 1) ? Y : X;
    const float* __restrict__ Q = (gram == 0) ? X : Y;

    __shared__ float sAT[64 * 65];   // [d][i], row 63 (i=63) zero pad
    __shared__ float sBT[64 * 65];

    const int tid = threadIdx.x;
    const float* pa = P + a * (LL * DD);
    const float* qb = Q + b * (LL * DD);

    // Load increments, transposed into smem
    for (int idx = tid; idx < MM * DD; idx += 128) {
        const int i = idx >> 6;       // 0..62
        const int d = idx & 63;
        sAT[d * 65 + i] = pa[(i + 1) * DD + d] - pa[i * DD + d];
        sBT[d * 65 + i] = qb[(i + 1) * DD + d] - qb[i * DD + d];
    }
    // zero-pad logical row i = 63
    if (tid < 64) {
        sAT[tid * 65 + 63] = 0.0f;
        sBT[tid * 65 + 63] = 0.0f;
    }
    __syncthreads();

    // 128 threads = 16 (rows) x 8 (cols); each computes a 4x8 tile of inc
    const int ty = tid >> 3;          // 0..15
    const int tx = tid & 7;           // 0..7
    const int i0 = ty * 4;
    const int j0 = tx * 8;

    float acc[4][8];
#pragma unroll
    for (int k = 0; k < 4; k++)
#pragma unroll
        for (int q = 0; q < 8; q++) acc[k][q] = 0.0f;

#pragma unroll 8
    for (int d = 0; d < 64; d++) {
        float av[4], bv[8];
#pragma unroll
        for (int k = 0; k < 4; k++) av[k] = sAT[d * 65 + i0 + k];
#pragma unroll
        for (int q = 0; q < 8; q++) bv[q] = sBT[d * 65 + j0 + q];
#pragma unroll
        for (int k = 0; k < 4; k++)
#pragma unroll
            for (int q = 0; q < 8; q++)
                acc[k][q] = fmaf(av[k], bv[q], acc[k][q]);
    }

    float* out = g_inc + (size_t)p * INC_STRIDE;
#pragma unroll
    for (int k = 0; k < 4; k++) {
        const int i = i0 + k;
        if (i < MM) {
            float4 v0 = make_float4(acc[k][0], acc[k][1], acc[k][2], acc[k][3]);
            float4 v1 = make_float4(acc[k][4], acc[k][5], acc[k][6], acc[k][7]);
            *reinterpret_cast<float4*>(out + i * 64 + j0)     = v0;
            *reinterpret_cast<float4*>(out + i * 64 + j0 + 4) = v1;
        }
    }
}

// ---------------------------------------------------------------------------
// Kernel 2: Goursat PDE recursion, one warp per pair.
// Row update is a prefix sum: new[j+1] = 1 + sum_{k<=j} c[k],
//   c[j] = prev[j+1] + prev[j]*(inc[i,j]-1).
// Lane l owns columns 2l, 2l+1 of the K row (64 entries). Warp-scan per row.
// ---------------------------------------------------------------------------
__global__ void __launch_bounds__(256) pde_kernel()
{
    const int warp = (blockIdx.x * blockDim.x + threadIdx.x) >> 5;
    const int lane = threadIdx.x & 31;
    if (warp >= NPAIRS) return;

    const int p = warp;
    const int gram = p / PER_GRAM;
    const int r = p % PER_GRAM;
    const int a = r / AP, b = r % AP;

    if (gram < 2 && a > b) {               // mirrored pair: contributes via weight 2
        if (lane == 0) g_K[p] = 0.0f;
        return;
    }

    float w;
    if (gram == 2) w = -2.0f / (float)PER_GRAM;
    else           w = ((a == b) ? 1.0f : 2.0f) / (float)PER_GRAM;

    const float* __restrict__ base = g_inc + (size_t)p * INC_STRIDE + 2 * lane;
    const bool last = (lane == 31);

    float prev0 = 1.0f;   // K[i][2l]
    float prev1 = 1.0f;   // K[i][2l+1]

    for (int i = 0; i < MM; i++) {
        const float2 inc = *reinterpret_cast<const float2*>(base + i * 64);
        const float prev2 = __shfl_down_sync(0xffffffffu, prev0, 1); // K[i][2l+2]

        const float c0 = fmaf(prev0, inc.x - 1.0f, prev1);
        const float c1 = last ? 0.0f : fmaf(prev1, inc.y - 1.0f, prev2);

        const float s = c0 + c1;
        float t = s;
#pragma unroll
        for (int off = 1; off < 32; off <<= 1) {
            const float u = __shfl_up_sync(0xffffffffu, t, off);
            if (lane >= off) t += u;
        }
        const float E = t - s;            // exclusive scan of pair sums

        prev0 = 1.0f + E;                 // new K[i+1][2l]
        prev1 = prev0 + c0;               // new K[i+1][2l+1]
    }

    if (last) g_K[p] = w * prev1;         // K[63][63], weighted
}

// ---------------------------------------------------------------------------
// Kernel 3: deterministic final reduction + mean((X0 - Y0)^2)
// ---------------------------------------------------------------------------
__global__ void __launch_bounds__(256) reduce_kernel(
    const float* __restrict__ X, const float* __restrict__ Y,
    float* __restrict__ out)
{
    __shared__ float sdata[256];
    const int tid = threadIdx.x;

    float s = 0.0f;
    for (int p = tid; p < NPAIRS; p += 256) s += g_K[p];

    float s2 = 0.0f;
    for (int idx = tid; idx < AP * DD; idx += 256) {
        const int aa = idx >> 6;
        const int d  = idx & 63;
        const float diff = X[aa * (LL * DD) + d] - Y[aa * (LL * DD) + d];
        s2 = fmaf(diff, diff, s2);
    }
    s += s2 * (1.0f / (float)(AP * DD));

    sdata[tid] = s;
    __syncthreads();
    for (int k = 128; k > 0; k >>= 1) {
        if (tid < k) sdata[tid] += sdata[tid + k];
        __syncthreads();
    }
    if (tid == 0) out[0] = sdata[0];
}

// ---------------------------------------------------------------------------
extern "C" void kernel_launch(void* const* d_in, const int* in_sizes, int n_in,
                              void* d_out, int out_size)
{
    const float* X = (const float*)d_in[0];
    const float* Y = (const float*)d_in[1];
    float* out = (float*)d_out;

    gemm_kernel<<<NPAIRS, 128>>>(X, Y);
    pde_kernel<<<(NPAIRS * 32) / 256, 256>>>();
    reduce_kernel<<<1, 256>>>(X, Y, out);
}